// round 3
// baseline (speedup 1.0000x reference)
#include <cuda_runtime.h>
#include <math.h>

#define Nn 50000
#define Ee 500000
#define Gg 32
#define Hh 4
#define Dd 40
#define HID 160
#define JK 320

// ---------------- scratch (device globals; no allocation allowed) ----------------
__device__ float    g_h0[(size_t)Nn*HID];        // input projection
__device__ float    g_q[(size_t)Nn*HID];
__device__ float    g_k[(size_t)Nn*HID];
__device__ float    g_v[(size_t)Nn*HID];
__device__ float    g_skip[(size_t)Nn*HID];
__device__ float    g_out[(size_t)Nn*HID];       // attention aggregation / reused as gate tmp
__device__ float    g_xc[(size_t)Nn*JK];         // JumpingKnowledge concat (layer outputs)
__device__ float    g_alpha[(size_t)Ee*Hh];      // edge logits -> exp values
__device__ unsigned g_amax[(size_t)Nn*Hh];       // encoded float max
__device__ float    g_denom[(size_t)Nn*Hh];
__device__ float    g_gate[Nn];                  // gate -> ge -> att
__device__ unsigned g_gmax[Gg];
__device__ float    g_gden[Gg];
__device__ float    g_pooled[Gg*JK];
__device__ int      g_ei32[(size_t)2*Ee];        // normalized int32 edge index
__device__ int      g_batch32[Nn];               // normalized int32 batch
__device__ int      g_is64;                      // dtype flag

// monotone float<->unsigned encoding for atomicMax on floats
__device__ __forceinline__ unsigned fenc(float f){
    unsigned u = __float_as_uint(f);
    return (u & 0x80000000u) ? ~u : (u | 0x80000000u);
}
__device__ __forceinline__ float fdec(unsigned e){
    return (e & 0x80000000u) ? __uint_as_float(e ^ 0x80000000u) : __uint_as_float(~e);
}

// ---------------- dtype detection + index normalization ----------------
// If edge_index is truly int64, every value read as int64 lies in [0, Nn).
// If it's int32 read as int64, adjacent pairs fuse -> huge values.
__global__ void k_detect(const void* __restrict__ ei){
    const long long* p = (const long long*)ei;
    int bad = 0;
    for (int i = threadIdx.x; i < 4096; i += 256){
        long long v = p[i];
        if (v < 0 || v >= Nn) bad = 1;
    }
    bad = __syncthreads_or(bad);
    if (threadIdx.x == 0) g_is64 = bad ? 0 : 1;
}

__global__ void k_convert(const void* __restrict__ ei, const void* __restrict__ batch){
    int idx = blockIdx.x*blockDim.x + threadIdx.x;
    int is64 = g_is64;
    if (idx < 2*Ee){
        g_ei32[idx] = is64 ? (int)((const long long*)ei)[idx]
                           : ((const int*)ei)[idx];
    }
    if (idx < Nn){
        g_batch32[idx] = is64 ? (int)((const long long*)batch)[idx]
                              : ((const int*)batch)[idx];
    }
}

// ---------------- input projection: h0 = x @ W_in + b_in ----------------
__global__ __launch_bounds__(HID) void k_input(const float* __restrict__ x,
                                               const float* __restrict__ W,
                                               const float* __restrict__ b){
    int n = blockIdx.x, c = threadIdx.x;
    __shared__ float xr[5];
    if (c < 5) xr[c] = x[n*5 + c];
    __syncthreads();
    float acc = b[c];
#pragma unroll
    for (int j = 0; j < 5; j++) acc = fmaf(xr[j], W[j*HID + c], acc);
    g_h0[(size_t)n*HID + c] = acc;
}

// ---------------- generic fp32 GEMM: [C0|C1|C2|C3] = A @ [B0|B1|B2|B3] + bias ----
// A: [M,K] row-major stride lda.  Each Bm: [K, matcols].  Each Cm: [M, matcols].
// Block tile 128x64, BK=16, thread tile 8x4, 256 threads.
__global__ __launch_bounds__(256) void k_gemm(
    const float* __restrict__ A, int lda, int M, int K,
    const float* __restrict__ B0, const float* __restrict__ B1,
    const float* __restrict__ B2, const float* __restrict__ B3,
    const float* __restrict__ bias0, const float* __restrict__ bias1,
    const float* __restrict__ bias2, const float* __restrict__ bias3,
    int matcols, int Ntot,
    float* __restrict__ C0, float* __restrict__ C1,
    float* __restrict__ C2, float* __restrict__ C3, int relu)
{
    __shared__ float As[16][132];  // transposed A tile, padded
    __shared__ float Bs[16][64];
    int tid = threadIdx.x;
    int bm = blockIdx.y * 128, bn = blockIdx.x * 64;
    int tm8 = (tid >> 4) << 3;   // 0..120
    int tn4 = (tid & 15) << 2;   // 0..60
    float acc[8][4];
#pragma unroll
    for (int i = 0; i < 8; i++)
#pragma unroll
        for (int j = 0; j < 4; j++) acc[i][j] = 0.f;

    int ar  = tid >> 2;          // 0..63
    int ac4 = (tid & 3) << 2;    // 0,4,8,12
    int bkr = tid >> 4;          // 0..15
    int bcc = (tid & 15) << 2;   // 0..60
    int bcol = bn + bcc;
    const float* Bm = nullptr;
    int bc2 = 0;
    if (bcol < Ntot){
        int m = bcol / matcols;
        bc2 = bcol - m * matcols;
        Bm = (m == 0) ? B0 : (m == 1) ? B1 : (m == 2) ? B2 : B3;
    }

    for (int k0 = 0; k0 < K; k0 += 16){
#pragma unroll
        for (int half = 0; half < 2; half++){
            int row = bm + ar + half*64;
            float4 av = make_float4(0.f,0.f,0.f,0.f);
            if (row < M) av = *reinterpret_cast<const float4*>(A + (size_t)row*lda + k0 + ac4);
            As[ac4+0][ar + half*64] = av.x;
            As[ac4+1][ar + half*64] = av.y;
            As[ac4+2][ar + half*64] = av.z;
            As[ac4+3][ar + half*64] = av.w;
        }
        {
            float4 bv = make_float4(0.f,0.f,0.f,0.f);
            if (Bm) bv = *reinterpret_cast<const float4*>(Bm + (size_t)(k0 + bkr)*matcols + bc2);
            *reinterpret_cast<float4*>(&Bs[bkr][bcc]) = bv;
        }
        __syncthreads();
#pragma unroll
        for (int kk = 0; kk < 16; kk++){
            float4 b4 = *reinterpret_cast<const float4*>(&Bs[kk][tn4]);
            float4 a0 = *reinterpret_cast<const float4*>(&As[kk][tm8]);
            float4 a1 = *reinterpret_cast<const float4*>(&As[kk][tm8+4]);
            float a_[8] = {a0.x,a0.y,a0.z,a0.w,a1.x,a1.y,a1.z,a1.w};
            float b_[4] = {b4.x,b4.y,b4.z,b4.w};
#pragma unroll
            for (int i = 0; i < 8; i++)
#pragma unroll
                for (int j = 0; j < 4; j++)
                    acc[i][j] = fmaf(a_[i], b_[j], acc[i][j]);
        }
        __syncthreads();
    }

#pragma unroll
    for (int j = 0; j < 4; j++){
        int col = bn + tn4 + j;
        if (col >= Ntot) continue;
        int m  = col / matcols;
        int c2 = col - m * matcols;
        const float* bp = (m == 0) ? bias0 : (m == 1) ? bias1 : (m == 2) ? bias2 : bias3;
        float* Cm      = (m == 0) ? C0 : (m == 1) ? C1 : (m == 2) ? C2 : C3;
        float bb = bp[c2];
#pragma unroll
        for (int i = 0; i < 8; i++){
            int row = bm + tm8 + i;
            if (row < M){
                float v = acc[i][j] + bb;
                if (relu) v = fmaxf(v, 0.f);
                Cm[(size_t)row*matcols + c2] = v;
            }
        }
    }
}

// ---------------- per-layer init ----------------
__global__ void k_init_layer(){
    int idx = blockIdx.x*blockDim.x + threadIdx.x;
    if (idx < Nn*HID) g_out[idx] = 0.f;
    if (idx < Nn*Hh){ g_amax[idx] = 0u; g_denom[idx] = 0.f; }
}

// ---------------- edge: alpha = q[dst].(k[src]+e)/sqrt(D), segment max -------
// one warp per edge; lane = head*8 + offset; each lane 5 strided elements.
__global__ __launch_bounds__(256) void k_edge_alpha(
    const float* __restrict__ ea,
    const float* __restrict__ We, const float* __restrict__ be)
{
    __shared__ float sWe[4*HID];
    __shared__ float sbe[HID];
    int t = threadIdx.x;
    for (int i = t; i < 4*HID; i += 256) sWe[i] = We[i];
    if (t < HID) sbe[t] = be[t];
    __syncthreads();
    int warp = t >> 5, lane = t & 31;
    int e = blockIdx.x*8 + warp;
    int src = g_ei32[e];
    int dst = g_ei32[Ee + e];
    float e0 = ea[e*4+0], e1 = ea[e*4+1], e2 = ea[e*4+2], e3 = ea[e*4+3];
    const float* qr = g_q + (size_t)dst*HID;
    const float* kr = g_k + (size_t)src*HID;
    int h = lane >> 3, o = lane & 7;
    int cb = h*Dd + o;
    float part = 0.f;
#pragma unroll
    for (int i = 0; i < 5; i++){
        int c = cb + 8*i;
        float ev = sbe[c] + e0*sWe[c] + e1*sWe[HID+c] + e2*sWe[2*HID+c] + e3*sWe[3*HID+c];
        part = fmaf(qr[c], kr[c] + ev, part);
    }
    part += __shfl_down_sync(0xffffffffu, part, 4, 8);
    part += __shfl_down_sync(0xffffffffu, part, 2, 8);
    part += __shfl_down_sync(0xffffffffu, part, 1, 8);
    if (o == 0){
        float a = part * 0.15811388300841897f;   // 1/sqrt(40)
        g_alpha[(size_t)e*4 + h] = a;
        atomicMax(&g_amax[(size_t)dst*4 + h], fenc(a));
    }
}

// ---------------- edge: ex = exp(alpha - amax[dst]), segment sum -------------
__global__ void k_edge_exp(){
    int idx = blockIdx.x*blockDim.x + threadIdx.x;
    if (idx >= Ee*Hh) return;
    int e = idx >> 2, h = idx & 3;
    int dst = g_ei32[Ee + e];
    float am = fdec(g_amax[(size_t)dst*4 + h]);
    float ex = expf(g_alpha[idx] - am);
    g_alpha[idx] = ex;
    atomicAdd(&g_denom[(size_t)dst*4 + h], ex);
}

// ---------------- edge: out[dst] += (v[src]+e) * ex/denom --------------------
__device__ __forceinline__ void aggr_f(
    const float* vr, float* orow, const float* sWe, const float* sbe,
    float e0, float e1, float e2, float e3, int f, float w)
{
    int c = f*4;
    float4 v4 = *reinterpret_cast<const float4*>(vr + c);
    float vv[4] = {v4.x, v4.y, v4.z, v4.w};
#pragma unroll
    for (int j = 0; j < 4; j++){
        int cc = c + j;
        float ev = sbe[cc] + e0*sWe[cc] + e1*sWe[HID+cc] + e2*sWe[2*HID+cc] + e3*sWe[3*HID+cc];
        atomicAdd(orow + cc, (vv[j] + ev)*w);
    }
}

__global__ __launch_bounds__(256) void k_edge_aggr(
    const float* __restrict__ ea,
    const float* __restrict__ We, const float* __restrict__ be)
{
    __shared__ float sWe[4*HID];
    __shared__ float sbe[HID];
    int t = threadIdx.x;
    for (int i = t; i < 4*HID; i += 256) sWe[i] = We[i];
    if (t < HID) sbe[t] = be[t];
    __syncthreads();
    int warp = t >> 5, lane = t & 31;
    int e = blockIdx.x*8 + warp;
    int src = g_ei32[e];
    int dst = g_ei32[Ee + e];
    float e0 = ea[e*4+0], e1 = ea[e*4+1], e2 = ea[e*4+2], e3 = ea[e*4+3];
    const float* vr = g_v + (size_t)src*HID;
    float* orow = g_out + (size_t)dst*HID;

    float wv = 0.f;
    if (lane < 4)
        wv = __fdividef(g_alpha[(size_t)e*4 + lane], g_denom[(size_t)dst*4 + lane]);
    int h1 = lane / 10;                              // head of float4 index `lane`
    float w1 = __shfl_sync(0xffffffffu, wv, h1);
    float w3 = __shfl_sync(0xffffffffu, wv, 3);      // head of float4 idx 32..39

    aggr_f(vr, orow, sWe, sbe, e0,e1,e2,e3, lane, w1);
    if (lane < 8) aggr_f(vr, orow, sWe, sbe, e0,e1,e2,e3, 32 + lane, w3);
}

// ---------------- beta gate + combine, write into xc slot --------------------
__global__ __launch_bounds__(256) void k_beta(const float* __restrict__ Wb, int l){
    int t = threadIdx.x, warp = t >> 5, lane = t & 31;
    int n = blockIdx.x*8 + warp;
    const float* o = g_out  + (size_t)n*HID;
    const float* r = g_skip + (size_t)n*HID;
    float oc[5], rc[5];
    float p = 0.f;
#pragma unroll
    for (int i = 0; i < 5; i++){
        int c = lane + 32*i;
        oc[i] = o[c]; rc[i] = r[c];
        p += oc[i]*Wb[c] + rc[i]*Wb[HID+c] + (oc[i]-rc[i])*Wb[2*HID+c];
    }
#pragma unroll
    for (int off = 16; off; off >>= 1) p += __shfl_xor_sync(0xffffffffu, p, off);
    float beta = 1.f/(1.f + expf(-p));
    float* hx = g_xc + (size_t)n*JK + (size_t)l*HID;
#pragma unroll
    for (int i = 0; i < 5; i++){
        int c = lane + 32*i;
        hx[c] = beta*rc[i] + (1.f - beta)*oc[i];
    }
}

// ---------------- pooling init ----------------
__global__ void k_init_pool(){
    int idx = blockIdx.x*blockDim.x + threadIdx.x;
    if (idx < Gg){ g_gmax[idx] = 0u; g_gden[idx] = 0.f; }
    if (idx < Gg*JK) g_pooled[idx] = 0.f;
}

// gate = tmp . Wg2 + bg2; segment max over graphs
__global__ __launch_bounds__(256) void k_gate(const float* __restrict__ Wg2,
                                              const float* __restrict__ bg2){
    int t = threadIdx.x, warp = t >> 5, lane = t & 31;
    int n = blockIdx.x*8 + warp;
    const float* tp = g_out + (size_t)n*HID;   // reused as relu(xc@Wg1) tmp
    float p = 0.f;
#pragma unroll
    for (int i = 0; i < 5; i++){
        int c = lane + 32*i;
        p = fmaf(tp[c], Wg2[c], p);
    }
#pragma unroll
    for (int off = 16; off; off >>= 1) p += __shfl_xor_sync(0xffffffffu, p, off);
    if (lane == 0){
        float gate = p + bg2[0];
        g_gate[n] = gate;
        atomicMax(&g_gmax[g_batch32[n]], fenc(gate));
    }
}

__global__ void k_ge(){
    __shared__ float s[Gg];
    int t = threadIdx.x;
    if (t < Gg) s[t] = 0.f;
    __syncthreads();
    int n = blockIdx.x*blockDim.x + t;
    if (n < Nn){
        int b = g_batch32[n];
        float ge = expf(g_gate[n] - fdec(g_gmax[b]));
        g_gate[n] = ge;
        atomicAdd(&s[b], ge);
    }
    __syncthreads();
    if (t < Gg) atomicAdd(&g_gden[t], s[t]);
}

__global__ void k_att(){
    int n = blockIdx.x*blockDim.x + threadIdx.x;
    if (n < Nn) g_gate[n] /= g_gden[g_batch32[n]];
}

// pooled[g] += att[n] * xc[n]  (batch sorted -> run-length accumulate)
__global__ __launch_bounds__(JK) void k_pool(){
    int c = threadIdx.x;
    int n0 = blockIdx.x*128;
    if (n0 >= Nn) return;
    int nend = min(n0 + 128, Nn);
    int curg = g_batch32[n0];
    float acc = 0.f;
    for (int n = n0; n < nend; n++){
        int g = g_batch32[n];
        if (g != curg){
            atomicAdd(&g_pooled[curg*JK + c], acc);
            acc = 0.f; curg = g;
        }
        acc = fmaf(g_gate[n], g_xc[(size_t)n*JK + c], acc);
    }
    atomicAdd(&g_pooled[curg*JK + c], acc);
}

// out = relu(pooled @ Wh1 + bh1) @ Wh2 + bh2
__global__ __launch_bounds__(JK) void k_final(const float* __restrict__ Wh1,
                                              const float* __restrict__ bh1,
                                              const float* __restrict__ Wh2,
                                              const float* __restrict__ bh2,
                                              float* __restrict__ outp){
    __shared__ float p[JK];
    __shared__ float t1[JK];
    int g = blockIdx.x, c = threadIdx.x;
    p[c] = g_pooled[g*JK + c];
    __syncthreads();
    float acc = bh1[c];
    for (int k = 0; k < JK; k++) acc = fmaf(p[k], Wh1[k*JK + c], acc);
    t1[c] = fmaxf(acc, 0.f);
    __syncthreads();
    int warp = c >> 5, lane = c & 31;
    if (warp < 6){
        float s = 0.f;
        for (int k = lane; k < JK; k += 32) s = fmaf(t1[k], Wh2[k*6 + warp], s);
#pragma unroll
        for (int off = 16; off; off >>= 1) s += __shfl_xor_sync(0xffffffffu, s, off);
        if (lane == 0) outp[g*6 + warp] = s + bh2[warp];
    }
}

// ---------------- host ----------------
extern "C" void kernel_launch(void* const* d_in, const int* in_sizes, int n_in,
                              void* d_out, int out_size){
    const float* x     = (const float*)d_in[0];
    const void*  ei    = d_in[1];
    const float* ea    = (const float*)d_in[2];
    const void*  batch = d_in[3];
    const float* W_in  = (const float*)d_in[4];
    const float* b_in  = (const float*)d_in[5];
    const float* Wq    = (const float*)d_in[6];
    const float* bq    = (const float*)d_in[7];
    const float* Wk    = (const float*)d_in[8];
    const float* bk    = (const float*)d_in[9];
    const float* Wv    = (const float*)d_in[10];
    const float* bv    = (const float*)d_in[11];
    const float* We    = (const float*)d_in[12];
    const float* be    = (const float*)d_in[13];
    const float* Wskip = (const float*)d_in[14];
    const float* bskip = (const float*)d_in[15];
    const float* Wbeta = (const float*)d_in[16];
    const float* Wg1   = (const float*)d_in[17];
    const float* bg1   = (const float*)d_in[18];
    const float* Wg2   = (const float*)d_in[19];
    const float* bg2   = (const float*)d_in[20];
    const float* Wh1   = (const float*)d_in[21];
    const float* bh1   = (const float*)d_in[22];
    const float* Wh2   = (const float*)d_in[23];
    const float* bh2   = (const float*)d_in[24];
    float* outp = (float*)d_out;

    void *ph0, *pxc, *pout, *pq, *pk, *pv, *ps;
    cudaGetSymbolAddress(&ph0, g_h0);
    cudaGetSymbolAddress(&pxc, g_xc);
    cudaGetSymbolAddress(&pout, g_out);
    cudaGetSymbolAddress(&pq, g_q);
    cudaGetSymbolAddress(&pk, g_k);
    cudaGetSymbolAddress(&pv, g_v);
    cudaGetSymbolAddress(&ps, g_skip);
    float* h0  = (float*)ph0;
    float* xc  = (float*)pxc;
    float* tmp = (float*)pout;
    float* qp  = (float*)pq;
    float* kp  = (float*)pk;
    float* vp  = (float*)pv;
    float* sp  = (float*)ps;

    k_detect<<<1, 256>>>(ei);
    k_convert<<<(2*Ee + 255)/256, 256>>>(ei, batch);
    k_input<<<Nn, HID>>>(x, W_in, b_in);

    for (int l = 0; l < 2; l++){
        const float* A = l ? xc : h0;
        int lda = l ? JK : HID;
        dim3 grid(640/64, (Nn + 127)/128);
        k_gemm<<<grid, 256>>>(A, lda, Nn, HID,
            Wq + l*HID*HID, Wk + l*HID*HID, Wv + l*HID*HID, Wskip + l*HID*HID,
            bq + l*HID, bk + l*HID, bv + l*HID, bskip + l*HID,
            HID, 4*HID, qp, kp, vp, sp, 0);
        k_init_layer<<<(Nn*HID + 255)/256, 256>>>();
        k_edge_alpha<<<Ee/8, 256>>>(ea, We + l*4*HID, be + l*HID);
        k_edge_exp<<<(Ee*Hh + 255)/256, 256>>>();
        k_edge_aggr<<<Ee/8, 256>>>(ea, We + l*4*HID, be + l*HID);
        k_beta<<<Nn/8, 256>>>(Wbeta + l*3*HID, l);
    }

    {
        dim3 grid((HID + 63)/64, (Nn + 127)/128);
        k_gemm<<<grid, 256>>>(xc, JK, Nn, JK,
            Wg1, Wg1, Wg1, Wg1, bg1, bg1, bg1, bg1,
            HID, HID, tmp, tmp, tmp, tmp, 1);
    }
    k_init_pool<<<40, 256>>>();
    k_gate<<<Nn/8, 256>>>(Wg2, bg2);
    k_ge<<<(Nn + 255)/256, 256>>>();
    k_att<<<(Nn + 255)/256, 256>>>();
    k_pool<<<(Nn + 127)/128, JK>>>();
    k_final<<<Gg, JK>>>(Wh1, bh1, Wh2, bh2, outp);
}

// round 4
// speedup vs baseline: 1.1562x; 1.1562x over previous
#include <cuda_runtime.h>
#include <math.h>

#define Nn 50000
#define Ee 500000
#define Gg 32
#define Hh 4
#define Dd 40
#define HID 160
#define JK 320
#define NBLK 196   // ceil(Nn/256)

// ---------------- scratch (device globals; no allocation allowed) ----------------
__device__ float    g_h0[(size_t)Nn*HID];
__device__ float    g_q[(size_t)Nn*HID];
__device__ float    g_k[(size_t)Nn*HID];
__device__ float    g_v[(size_t)Nn*HID];
__device__ float    g_skip[(size_t)Nn*HID];
__device__ float    g_out[(size_t)Nn*HID];       // attention aggregation / gate tmp
__device__ float    g_xc[(size_t)Nn*JK];
__device__ float    g_alpha[(size_t)Ee*Hh];      // logits -> normalized weights
__device__ float    g_gate[Nn];
__device__ unsigned g_gmax[Gg];
__device__ float    g_gden[Gg];
__device__ float    g_pooled[Gg*JK];
__device__ int      g_ei32[(size_t)2*Ee];
__device__ int      g_batch32[Nn];
__device__ int      g_is64;
// CSR by destination
__device__ int      g_cnt[Nn];
__device__ int      g_rowptr[Nn+1];
__device__ int      g_fill[Nn];
__device__ int      g_eid[Ee];
__device__ int      g_bsum[NBLK];
__device__ int      g_boff[NBLK];

__device__ __forceinline__ unsigned fenc(float f){
    unsigned u = __float_as_uint(f);
    return (u & 0x80000000u) ? ~u : (u | 0x80000000u);
}
__device__ __forceinline__ float fdec(unsigned e){
    return (e & 0x80000000u) ? __uint_as_float(e ^ 0x80000000u) : __uint_as_float(~e);
}

// ---------------- dtype detection + index normalization ----------------
__global__ void k_detect(const void* __restrict__ ei){
    const long long* p = (const long long*)ei;
    int bad = 0;
    for (int i = threadIdx.x; i < 4096; i += 256){
        long long v = p[i];
        if (v < 0 || v >= Nn) bad = 1;
    }
    bad = __syncthreads_or(bad);
    if (threadIdx.x == 0) g_is64 = bad ? 0 : 1;
}

__global__ void k_convert(const void* __restrict__ ei, const void* __restrict__ batch){
    int idx = blockIdx.x*blockDim.x + threadIdx.x;
    int is64 = g_is64;
    if (idx < 2*Ee){
        g_ei32[idx] = is64 ? (int)((const long long*)ei)[idx]
                           : ((const int*)ei)[idx];
    }
    if (idx < Nn){
        g_batch32[idx] = is64 ? (int)((const long long*)batch)[idx]
                              : ((const int*)batch)[idx];
        g_cnt[idx] = 0;
    }
}

// ---------------- CSR build ----------------
__global__ void k_count(){
    int e = blockIdx.x*blockDim.x + threadIdx.x;
    if (e < Ee) atomicAdd(&g_cnt[g_ei32[Ee + e]], 1);
}

__global__ __launch_bounds__(256) void k_scan1(){
    __shared__ int s[256];
    int t = threadIdx.x;
    int idx = blockIdx.x*256 + t;
    int v = (idx < Nn) ? g_cnt[idx] : 0;
    s[t] = v; __syncthreads();
#pragma unroll
    for (int off = 1; off < 256; off <<= 1){
        int x = (t >= off) ? s[t-off] : 0;
        __syncthreads();
        s[t] += x;
        __syncthreads();
    }
    if (idx < Nn) g_rowptr[idx] = s[t] - v;   // exclusive within block
    if (t == 255) g_bsum[blockIdx.x] = s[255];
}

__global__ __launch_bounds__(256) void k_scan2(){
    __shared__ int s[256];
    int t = threadIdx.x;
    int v = (t < NBLK) ? g_bsum[t] : 0;
    s[t] = v; __syncthreads();
#pragma unroll
    for (int off = 1; off < 256; off <<= 1){
        int x = (t >= off) ? s[t-off] : 0;
        __syncthreads();
        s[t] += x;
        __syncthreads();
    }
    if (t < NBLK) g_boff[t] = s[t] - v;       // exclusive
}

__global__ void k_scan3(){
    int idx = blockIdx.x*blockDim.x + threadIdx.x;
    if (idx < Nn){
        int r = g_rowptr[idx] + g_boff[idx >> 8];
        g_rowptr[idx] = r;
        g_fill[idx] = r;
    }
    if (idx == 0) g_rowptr[Nn] = Ee;
}

__global__ void k_fill(){
    int e = blockIdx.x*blockDim.x + threadIdx.x;
    if (e < Ee){
        int slot = atomicAdd(&g_fill[g_ei32[Ee + e]], 1);
        g_eid[slot] = e;
    }
}

// ---------------- input projection ----------------
__global__ __launch_bounds__(HID) void k_input(const float* __restrict__ x,
                                               const float* __restrict__ W,
                                               const float* __restrict__ b){
    int n = blockIdx.x, c = threadIdx.x;
    __shared__ float xr[5];
    if (c < 5) xr[c] = x[n*5 + c];
    __syncthreads();
    float acc = b[c];
#pragma unroll
    for (int j = 0; j < 5; j++) acc = fmaf(xr[j], W[j*HID + c], acc);
    g_h0[(size_t)n*HID + c] = acc;
}

// ---------------- generic fp32 GEMM (unchanged) ----------------
__global__ __launch_bounds__(256) void k_gemm(
    const float* __restrict__ A, int lda, int M, int K,
    const float* __restrict__ B0, const float* __restrict__ B1,
    const float* __restrict__ B2, const float* __restrict__ B3,
    const float* __restrict__ bias0, const float* __restrict__ bias1,
    const float* __restrict__ bias2, const float* __restrict__ bias3,
    int matcols, int Ntot,
    float* __restrict__ C0, float* __restrict__ C1,
    float* __restrict__ C2, float* __restrict__ C3, int relu)
{
    __shared__ float As[16][132];
    __shared__ float Bs[16][64];
    int tid = threadIdx.x;
    int bm = blockIdx.y * 128, bn = blockIdx.x * 64;
    int tm8 = (tid >> 4) << 3;
    int tn4 = (tid & 15) << 2;
    float acc[8][4];
#pragma unroll
    for (int i = 0; i < 8; i++)
#pragma unroll
        for (int j = 0; j < 4; j++) acc[i][j] = 0.f;

    int ar  = tid >> 2;
    int ac4 = (tid & 3) << 2;
    int bkr = tid >> 4;
    int bcc = (tid & 15) << 2;
    int bcol = bn + bcc;
    const float* Bm = nullptr;
    int bc2 = 0;
    if (bcol < Ntot){
        int m = bcol / matcols;
        bc2 = bcol - m * matcols;
        Bm = (m == 0) ? B0 : (m == 1) ? B1 : (m == 2) ? B2 : B3;
    }

    for (int k0 = 0; k0 < K; k0 += 16){
#pragma unroll
        for (int half = 0; half < 2; half++){
            int row = bm + ar + half*64;
            float4 av = make_float4(0.f,0.f,0.f,0.f);
            if (row < M) av = *reinterpret_cast<const float4*>(A + (size_t)row*lda + k0 + ac4);
            As[ac4+0][ar + half*64] = av.x;
            As[ac4+1][ar + half*64] = av.y;
            As[ac4+2][ar + half*64] = av.z;
            As[ac4+3][ar + half*64] = av.w;
        }
        {
            float4 bv = make_float4(0.f,0.f,0.f,0.f);
            if (Bm) bv = *reinterpret_cast<const float4*>(Bm + (size_t)(k0 + bkr)*matcols + bc2);
            *reinterpret_cast<float4*>(&Bs[bkr][bcc]) = bv;
        }
        __syncthreads();
#pragma unroll
        for (int kk = 0; kk < 16; kk++){
            float4 b4 = *reinterpret_cast<const float4*>(&Bs[kk][tn4]);
            float4 a0 = *reinterpret_cast<const float4*>(&As[kk][tm8]);
            float4 a1 = *reinterpret_cast<const float4*>(&As[kk][tm8+4]);
            float a_[8] = {a0.x,a0.y,a0.z,a0.w,a1.x,a1.y,a1.z,a1.w};
            float b_[4] = {b4.x,b4.y,b4.z,b4.w};
#pragma unroll
            for (int i = 0; i < 8; i++)
#pragma unroll
                for (int j = 0; j < 4; j++)
                    acc[i][j] = fmaf(a_[i], b_[j], acc[i][j]);
        }
        __syncthreads();
    }

#pragma unroll
    for (int j = 0; j < 4; j++){
        int col = bn + tn4 + j;
        if (col >= Ntot) continue;
        int m  = col / matcols;
        int c2 = col - m * matcols;
        const float* bp = (m == 0) ? bias0 : (m == 1) ? bias1 : (m == 2) ? bias2 : bias3;
        float* Cm      = (m == 0) ? C0 : (m == 1) ? C1 : (m == 2) ? C2 : C3;
        float bb = bp[c2];
#pragma unroll
        for (int i = 0; i < 8; i++){
            int row = bm + tm8 + i;
            if (row < M){
                float v = acc[i][j] + bb;
                if (relu) v = fmaxf(v, 0.f);
                Cm[(size_t)row*matcols + c2] = v;
            }
        }
    }
}

// ---------------- edge: alpha logits ----------------
__global__ __launch_bounds__(256) void k_edge_alpha(
    const float* __restrict__ ea,
    const float* __restrict__ We, const float* __restrict__ be)
{
    __shared__ float sWe[4*HID];
    __shared__ float sbe[HID];
    int t = threadIdx.x;
    for (int i = t; i < 4*HID; i += 256) sWe[i] = We[i];
    if (t < HID) sbe[t] = be[t];
    __syncthreads();
    int warp = t >> 5, lane = t & 31;
    int e = blockIdx.x*8 + warp;
    int src = g_ei32[e];
    int dst = g_ei32[Ee + e];
    float e0 = ea[e*4+0], e1 = ea[e*4+1], e2 = ea[e*4+2], e3 = ea[e*4+3];
    const float* qr = g_q + (size_t)dst*HID;
    const float* kr = g_k + (size_t)src*HID;
    int h = lane >> 3, o = lane & 7;
    int cb = h*Dd + o;
    float part = 0.f;
#pragma unroll
    for (int i = 0; i < 5; i++){
        int c = cb + 8*i;
        float ev = sbe[c] + e0*sWe[c] + e1*sWe[HID+c] + e2*sWe[2*HID+c] + e3*sWe[3*HID+c];
        part = fmaf(qr[c], kr[c] + ev, part);
    }
    part += __shfl_down_sync(0xffffffffu, part, 4, 8);
    part += __shfl_down_sync(0xffffffffu, part, 2, 8);
    part += __shfl_down_sync(0xffffffffu, part, 1, 8);
    if (o == 0)
        g_alpha[(size_t)e*4 + h] = part * 0.15811388300841897f;  // 1/sqrt(40)
}

// ---------------- per-node softmax over incoming edges (warp per node) ------
__global__ __launch_bounds__(256) void k_node_soft(){
    int t = threadIdx.x, warp = t >> 5, lane = t & 31;
    int n = blockIdx.x*8 + warp;
    int beg = g_rowptr[n], end = g_rowptr[n+1];
    int deg = end - beg;
    if (deg == 0) return;
    float4* al4 = reinterpret_cast<float4*>(g_alpha);

    float m0=-3.4e38f, m1=-3.4e38f, m2=-3.4e38f, m3=-3.4e38f;
    for (int i = lane; i < deg; i += 32){
        float4 a = al4[g_eid[beg + i]];
        m0 = fmaxf(m0, a.x); m1 = fmaxf(m1, a.y);
        m2 = fmaxf(m2, a.z); m3 = fmaxf(m3, a.w);
    }
#pragma unroll
    for (int off = 16; off; off >>= 1){
        m0 = fmaxf(m0, __shfl_xor_sync(0xffffffffu, m0, off));
        m1 = fmaxf(m1, __shfl_xor_sync(0xffffffffu, m1, off));
        m2 = fmaxf(m2, __shfl_xor_sync(0xffffffffu, m2, off));
        m3 = fmaxf(m3, __shfl_xor_sync(0xffffffffu, m3, off));
    }
    float s0=0.f, s1=0.f, s2=0.f, s3=0.f;
    for (int i = lane; i < deg; i += 32){
        int e = g_eid[beg + i];
        float4 a = al4[e];
        a.x = expf(a.x - m0); a.y = expf(a.y - m1);
        a.z = expf(a.z - m2); a.w = expf(a.w - m3);
        s0 += a.x; s1 += a.y; s2 += a.z; s3 += a.w;
        al4[e] = a;
    }
#pragma unroll
    for (int off = 16; off; off >>= 1){
        s0 += __shfl_xor_sync(0xffffffffu, s0, off);
        s1 += __shfl_xor_sync(0xffffffffu, s1, off);
        s2 += __shfl_xor_sync(0xffffffffu, s2, off);
        s3 += __shfl_xor_sync(0xffffffffu, s3, off);
    }
    float r0 = 1.f/s0, r1 = 1.f/s1, r2 = 1.f/s2, r3 = 1.f/s3;
    for (int i = lane; i < deg; i += 32){
        int e = g_eid[beg + i];
        float4 a = al4[e];
        a.x *= r0; a.y *= r1; a.z *= r2; a.w *= r3;
        al4[e] = a;
    }
}

// ---------------- per-node aggregation (block of 160 threads per node) ------
#define ECH 64
__global__ __launch_bounds__(HID) void k_node_aggr(
    const float* __restrict__ ea,
    const float* __restrict__ We, const float* __restrict__ be)
{
    __shared__ float sWe[4*HID];
    __shared__ float sbe[HID];
    __shared__ float4 s_ea[ECH];
    __shared__ float4 s_a[ECH];
    __shared__ int    s_src[ECH];
    int c = threadIdx.x;
    int n = blockIdx.x;
    for (int i = c; i < 4*HID; i += HID) sWe[i] = We[i];
    sbe[c] = be[c];
    int beg = g_rowptr[n], end = g_rowptr[n+1];
    int h = c / Dd;
    float acc = 0.f;
    const float4* ea4 = reinterpret_cast<const float4*>(ea);
    const float4* al4 = reinterpret_cast<const float4*>(g_alpha);

    for (int base = beg; base < end; base += ECH){
        int m = min(ECH, end - base);
        __syncthreads();
        if (c < m){
            int e = g_eid[base + c];
            s_src[c] = g_ei32[e];
            s_ea[c]  = ea4[e];
            s_a[c]   = al4[e];
        }
        __syncthreads();
        for (int j = 0; j < m; j++){
            float4 ej = s_ea[j];
            float w = reinterpret_cast<const float*>(&s_a[j])[h];
            float ev = sbe[c] + ej.x*sWe[c] + ej.y*sWe[HID+c]
                     + ej.z*sWe[2*HID+c] + ej.w*sWe[3*HID+c];
            acc = fmaf(g_v[(size_t)s_src[j]*HID + c] + ev, w, acc);
        }
    }
    g_out[(size_t)n*HID + c] = acc;
}

// ---------------- beta gate + combine ----------------
__global__ __launch_bounds__(256) void k_beta(const float* __restrict__ Wb, int l){
    int t = threadIdx.x, warp = t >> 5, lane = t & 31;
    int n = blockIdx.x*8 + warp;
    const float* o = g_out  + (size_t)n*HID;
    const float* r = g_skip + (size_t)n*HID;
    float oc[5], rc[5];
    float p = 0.f;
#pragma unroll
    for (int i = 0; i < 5; i++){
        int c = lane + 32*i;
        oc[i] = o[c]; rc[i] = r[c];
        p += oc[i]*Wb[c] + rc[i]*Wb[HID+c] + (oc[i]-rc[i])*Wb[2*HID+c];
    }
#pragma unroll
    for (int off = 16; off; off >>= 1) p += __shfl_xor_sync(0xffffffffu, p, off);
    float beta = 1.f/(1.f + expf(-p));
    float* hx = g_xc + (size_t)n*JK + (size_t)l*HID;
#pragma unroll
    for (int i = 0; i < 5; i++){
        int c = lane + 32*i;
        hx[c] = beta*rc[i] + (1.f - beta)*oc[i];
    }
}

// ---------------- pooling ----------------
__global__ void k_init_pool(){
    int idx = blockIdx.x*blockDim.x + threadIdx.x;
    if (idx < Gg){ g_gmax[idx] = 0u; g_gden[idx] = 0.f; }
    if (idx < Gg*JK) g_pooled[idx] = 0.f;
}

__global__ __launch_bounds__(256) void k_gate(const float* __restrict__ Wg2,
                                              const float* __restrict__ bg2){
    int t = threadIdx.x, warp = t >> 5, lane = t & 31;
    int n = blockIdx.x*8 + warp;
    const float* tp = g_out + (size_t)n*HID;
    float p = 0.f;
#pragma unroll
    for (int i = 0; i < 5; i++){
        int c = lane + 32*i;
        p = fmaf(tp[c], Wg2[c], p);
    }
#pragma unroll
    for (int off = 16; off; off >>= 1) p += __shfl_xor_sync(0xffffffffu, p, off);
    if (lane == 0){
        float gate = p + bg2[0];
        g_gate[n] = gate;
        atomicMax(&g_gmax[g_batch32[n]], fenc(gate));
    }
}

__global__ void k_ge(){
    __shared__ float s[Gg];
    int t = threadIdx.x;
    if (t < Gg) s[t] = 0.f;
    __syncthreads();
    int n = blockIdx.x*blockDim.x + t;
    if (n < Nn){
        int b = g_batch32[n];
        float ge = expf(g_gate[n] - fdec(g_gmax[b]));
        g_gate[n] = ge;
        atomicAdd(&s[b], ge);
    }
    __syncthreads();
    if (t < Gg) atomicAdd(&g_gden[t], s[t]);
}

__global__ void k_att(){
    int n = blockIdx.x*blockDim.x + threadIdx.x;
    if (n < Nn) g_gate[n] /= g_gden[g_batch32[n]];
}

__global__ __launch_bounds__(JK) void k_pool(){
    int c = threadIdx.x;
    int n0 = blockIdx.x*128;
    if (n0 >= Nn) return;
    int nend = min(n0 + 128, Nn);
    int curg = g_batch32[n0];
    float acc = 0.f;
    for (int n = n0; n < nend; n++){
        int g = g_batch32[n];
        if (g != curg){
            atomicAdd(&g_pooled[curg*JK + c], acc);
            acc = 0.f; curg = g;
        }
        acc = fmaf(g_gate[n], g_xc[(size_t)n*JK + c], acc);
    }
    atomicAdd(&g_pooled[curg*JK + c], acc);
}

__global__ __launch_bounds__(JK) void k_final(const float* __restrict__ Wh1,
                                              const float* __restrict__ bh1,
                                              const float* __restrict__ Wh2,
                                              const float* __restrict__ bh2,
                                              float* __restrict__ outp){
    __shared__ float p[JK];
    __shared__ float t1[JK];
    int g = blockIdx.x, c = threadIdx.x;
    p[c] = g_pooled[g*JK + c];
    __syncthreads();
    float acc = bh1[c];
    for (int k = 0; k < JK; k++) acc = fmaf(p[k], Wh1[k*JK + c], acc);
    t1[c] = fmaxf(acc, 0.f);
    __syncthreads();
    int warp = c >> 5, lane = c & 31;
    if (warp < 6){
        float s = 0.f;
        for (int k = lane; k < JK; k += 32) s = fmaf(t1[k], Wh2[k*6 + warp], s);
#pragma unroll
        for (int off = 16; off; off >>= 1) s += __shfl_xor_sync(0xffffffffu, s, off);
        if (lane == 0) outp[g*6 + warp] = s + bh2[warp];
    }
}

// ---------------- host ----------------
extern "C" void kernel_launch(void* const* d_in, const int* in_sizes, int n_in,
                              void* d_out, int out_size){
    const float* x     = (const float*)d_in[0];
    const void*  ei    = d_in[1];
    const float* ea    = (const float*)d_in[2];
    const void*  batch = d_in[3];
    const float* W_in  = (const float*)d_in[4];
    const float* b_in  = (const float*)d_in[5];
    const float* Wq    = (const float*)d_in[6];
    const float* bq    = (const float*)d_in[7];
    const float* Wk    = (const float*)d_in[8];
    const float* bk    = (const float*)d_in[9];
    const float* Wv    = (const float*)d_in[10];
    const float* bv    = (const float*)d_in[11];
    const float* We    = (const float*)d_in[12];
    const float* be    = (const float*)d_in[13];
    const float* Wskip = (const float*)d_in[14];
    const float* bskip = (const float*)d_in[15];
    const float* Wbeta = (const float*)d_in[16];
    const float* Wg1   = (const float*)d_in[17];
    const float* bg1   = (const float*)d_in[18];
    const float* Wg2   = (const float*)d_in[19];
    const float* bg2   = (const float*)d_in[20];
    const float* Wh1   = (const float*)d_in[21];
    const float* bh1   = (const float*)d_in[22];
    const float* Wh2   = (const float*)d_in[23];
    const float* bh2   = (const float*)d_in[24];
    float* outp = (float*)d_out;

    void *ph0, *pxc, *pout, *pq, *pk, *pv, *ps;
    cudaGetSymbolAddress(&ph0, g_h0);
    cudaGetSymbolAddress(&pxc, g_xc);
    cudaGetSymbolAddress(&pout, g_out);
    cudaGetSymbolAddress(&pq, g_q);
    cudaGetSymbolAddress(&pk, g_k);
    cudaGetSymbolAddress(&pv, g_v);
    cudaGetSymbolAddress(&ps, g_skip);
    float* h0  = (float*)ph0;
    float* xc  = (float*)pxc;
    float* tmp = (float*)pout;
    float* qp  = (float*)pq;
    float* kp  = (float*)pk;
    float* vp  = (float*)pv;
    float* sp  = (float*)ps;

    k_detect<<<1, 256>>>(ei);
    k_convert<<<(2*Ee + 255)/256, 256>>>(ei, batch);
    // CSR build
    k_count<<<(Ee + 255)/256, 256>>>();
    k_scan1<<<NBLK, 256>>>();
    k_scan2<<<1, 256>>>();
    k_scan3<<<NBLK, 256>>>();
    k_fill<<<(Ee + 255)/256, 256>>>();

    k_input<<<Nn, HID>>>(x, W_in, b_in);

    for (int l = 0; l < 2; l++){
        const float* A = l ? xc : h0;
        int lda = l ? JK : HID;
        dim3 grid(640/64, (Nn + 127)/128);
        k_gemm<<<grid, 256>>>(A, lda, Nn, HID,
            Wq + l*HID*HID, Wk + l*HID*HID, Wv + l*HID*HID, Wskip + l*HID*HID,
            bq + l*HID, bk + l*HID, bv + l*HID, bskip + l*HID,
            HID, 4*HID, qp, kp, vp, sp, 0);
        k_edge_alpha<<<Ee/8, 256>>>(ea, We + l*4*HID, be + l*HID);
        k_node_soft<<<Nn/8, 256>>>();
        k_node_aggr<<<Nn, HID>>>(ea, We + l*4*HID, be + l*HID);
        k_beta<<<Nn/8, 256>>>(Wbeta + l*3*HID, l);
    }

    {
        dim3 grid((HID + 63)/64, (Nn + 127)/128);
        k_gemm<<<grid, 256>>>(xc, JK, Nn, JK,
            Wg1, Wg1, Wg1, Wg1, bg1, bg1, bg1, bg1,
            HID, HID, tmp, tmp, tmp, tmp, 1);
    }
    k_init_pool<<<40, 256>>>();
    k_gate<<<Nn/8, 256>>>(Wg2, bg2);
    k_ge<<<(Nn + 255)/256, 256>>>();
    k_att<<<(Nn + 255)/256, 256>>>();
    k_pool<<<(Nn + 127)/128, JK>>>();
    k_final<<<Gg, JK>>>(Wh1, bh1, Wh2, bh2, outp);
}

// round 5
// speedup vs baseline: 1.1585x; 1.0020x over previous
#include <cuda_runtime.h>
#include <math.h>

#define Nn 50000
#define Ee 500000
#define Gg 32
#define Hh 4
#define Dd 40
#define HID 160
#define JK 320
#define NBLK 196   // ceil(Nn/256)

// ---------------- scratch (device globals; no allocation allowed) ----------------
__device__ float    g_h0[(size_t)Nn*HID];
__device__ float    g_q[(size_t)Nn*HID];
__device__ float    g_k[(size_t)Nn*HID];
__device__ float    g_v[(size_t)Nn*HID];
__device__ float    g_skip[(size_t)Nn*HID];
__device__ float    g_out[(size_t)Nn*HID];       // attention aggregation / gate tmp
__device__ float    g_xc[(size_t)Nn*JK];
__device__ float    g_alpha[(size_t)Ee*Hh];      // logits -> normalized weights
__device__ float    g_gate[Nn];
__device__ unsigned g_gmax[Gg];
__device__ float    g_gden[Gg];
__device__ float    g_pooled[Gg*JK];
__device__ int      g_ei32[(size_t)2*Ee];
__device__ int      g_batch32[Nn];
__device__ int      g_is64;
// CSR by destination
__device__ int      g_cnt[Nn];
__device__ int      g_rowptr[Nn+1];
__device__ int      g_fill[Nn];
__device__ int      g_eid[Ee];
__device__ int      g_bsum[NBLK];
__device__ int      g_boff[NBLK];

__device__ __forceinline__ unsigned fenc(float f){
    unsigned u = __float_as_uint(f);
    return (u & 0x80000000u) ? ~u : (u | 0x80000000u);
}
__device__ __forceinline__ float fdec(unsigned e){
    return (e & 0x80000000u) ? __uint_as_float(e ^ 0x80000000u) : __uint_as_float(~e);
}

// ---------------- dtype detection + index normalization ----------------
__global__ void k_detect(const void* __restrict__ ei){
    const long long* p = (const long long*)ei;
    int bad = 0;
    for (int i = threadIdx.x; i < 4096; i += 256){
        long long v = p[i];
        if (v < 0 || v >= Nn) bad = 1;
    }
    bad = __syncthreads_or(bad);
    if (threadIdx.x == 0) g_is64 = bad ? 0 : 1;
}

__global__ void k_convert(const void* __restrict__ ei, const void* __restrict__ batch){
    int idx = blockIdx.x*blockDim.x + threadIdx.x;
    int is64 = g_is64;
    if (idx < 2*Ee){
        g_ei32[idx] = is64 ? (int)((const long long*)ei)[idx]
                           : ((const int*)ei)[idx];
    }
    if (idx < Nn){
        g_batch32[idx] = is64 ? (int)((const long long*)batch)[idx]
                              : ((const int*)batch)[idx];
        g_cnt[idx] = 0;
    }
}

// ---------------- CSR build ----------------
__global__ void k_count(){
    int e = blockIdx.x*blockDim.x + threadIdx.x;
    if (e < Ee) atomicAdd(&g_cnt[g_ei32[Ee + e]], 1);
}

__global__ __launch_bounds__(256) void k_scan1(){
    __shared__ int s[256];
    int t = threadIdx.x;
    int idx = blockIdx.x*256 + t;
    int v = (idx < Nn) ? g_cnt[idx] : 0;
    s[t] = v; __syncthreads();
#pragma unroll
    for (int off = 1; off < 256; off <<= 1){
        int x = (t >= off) ? s[t-off] : 0;
        __syncthreads();
        s[t] += x;
        __syncthreads();
    }
    if (idx < Nn) g_rowptr[idx] = s[t] - v;
    if (t == 255) g_bsum[blockIdx.x] = s[255];
}

__global__ __launch_bounds__(256) void k_scan2(){
    __shared__ int s[256];
    int t = threadIdx.x;
    int v = (t < NBLK) ? g_bsum[t] : 0;
    s[t] = v; __syncthreads();
#pragma unroll
    for (int off = 1; off < 256; off <<= 1){
        int x = (t >= off) ? s[t-off] : 0;
        __syncthreads();
        s[t] += x;
        __syncthreads();
    }
    if (t < NBLK) g_boff[t] = s[t] - v;
}

__global__ void k_scan3(){
    int idx = blockIdx.x*blockDim.x + threadIdx.x;
    if (idx < Nn){
        int r = g_rowptr[idx] + g_boff[idx >> 8];
        g_rowptr[idx] = r;
        g_fill[idx] = r;
    }
    if (idx == 0) g_rowptr[Nn] = Ee;
}

__global__ void k_fill(){
    int e = blockIdx.x*blockDim.x + threadIdx.x;
    if (e < Ee){
        int slot = atomicAdd(&g_fill[g_ei32[Ee + e]], 1);
        g_eid[slot] = e;
    }
}

// ---------------- input projection ----------------
__global__ __launch_bounds__(HID) void k_input(const float* __restrict__ x,
                                               const float* __restrict__ W,
                                               const float* __restrict__ b){
    int n = blockIdx.x, c = threadIdx.x;
    __shared__ float xr[5];
    if (c < 5) xr[c] = x[n*5 + c];
    __syncthreads();
    float acc = b[c];
#pragma unroll
    for (int j = 0; j < 5; j++) acc = fmaf(xr[j], W[j*HID + c], acc);
    g_h0[(size_t)n*HID + c] = acc;
}

// ---------------- high-perf fp32 GEMM: 128x128 tile, 8x8/thread, double buffer ----
// A: [M,K] stride lda.  B columns 0..Ntot-1 select among [B0|B1|B2|B3] (matcols each).
// Requires: K % 8 == 0, Ntot % 4 == 0, matcols % 4 == 0, tile N exact (grid.x*128 cols checked).
__global__ __launch_bounds__(256) void k_gemm2(
    const float* __restrict__ A, int lda, int M, int K,
    const float* __restrict__ B0, const float* __restrict__ B1,
    const float* __restrict__ B2, const float* __restrict__ B3,
    const float* __restrict__ bias0, const float* __restrict__ bias1,
    const float* __restrict__ bias2, const float* __restrict__ bias3,
    int matcols, int Ntot,
    float* __restrict__ C0, float* __restrict__ C1,
    float* __restrict__ C2, float* __restrict__ C3)
{
    __shared__ float As[2][8][132];
    __shared__ float Bs[2][8][132];
    int tid = threadIdx.x;
    int bm = blockIdx.y*128, bn = blockIdx.x*128;

    int arow = tid >> 1;            // 0..127
    int acol = (tid & 1) << 2;      // 0,4
    int bkr  = tid >> 5;            // 0..7
    int bnc  = (tid & 31) << 2;     // 0..124

    int bcol = bn + bnc;
    const float* Bm = nullptr; int bc2 = 0;
    if (bcol < Ntot){
        int m = bcol / matcols;
        bc2 = bcol - m*matcols;
        Bm = (m==0)?B0:(m==1)?B1:(m==2)?B2:B3;
    }

    int tm = (tid >> 4) << 3;       // 0..120
    int tn = (tid & 15) << 3;       // 0..120

    float acc[8][8];
#pragma unroll
    for (int i = 0; i < 8; i++)
#pragma unroll
        for (int j = 0; j < 8; j++) acc[i][j] = 0.f;

    int aok = (bm + arow) < M;
    const float* Aptr = A + (size_t)(bm + arow)*lda + acol;

    float4 av = make_float4(0,0,0,0), bv = make_float4(0,0,0,0);
    if (aok) av = *reinterpret_cast<const float4*>(Aptr);
    if (Bm)  bv = *reinterpret_cast<const float4*>(Bm + (size_t)bkr*matcols + bc2);
    As[0][acol+0][arow]=av.x; As[0][acol+1][arow]=av.y;
    As[0][acol+2][arow]=av.z; As[0][acol+3][arow]=av.w;
    *reinterpret_cast<float4*>(&Bs[0][bkr][bnc]) = bv;
    __syncthreads();

    int nt = K >> 3;
    for (int t = 0; t < nt; t++){
        int buf = t & 1;
        if (t+1 < nt){
            int k0 = (t+1) << 3;
            av = make_float4(0,0,0,0); bv = make_float4(0,0,0,0);
            if (aok) av = *reinterpret_cast<const float4*>(Aptr + k0);
            if (Bm)  bv = *reinterpret_cast<const float4*>(Bm + (size_t)(k0+bkr)*matcols + bc2);
        }
#pragma unroll
        for (int kk = 0; kk < 8; kk++){
            float4 a0 = *reinterpret_cast<const float4*>(&As[buf][kk][tm]);
            float4 a1 = *reinterpret_cast<const float4*>(&As[buf][kk][tm+4]);
            float4 b0 = *reinterpret_cast<const float4*>(&Bs[buf][kk][tn]);
            float4 b1 = *reinterpret_cast<const float4*>(&Bs[buf][kk][tn+4]);
            float a_[8] = {a0.x,a0.y,a0.z,a0.w,a1.x,a1.y,a1.z,a1.w};
            float b_[8] = {b0.x,b0.y,b0.z,b0.w,b1.x,b1.y,b1.z,b1.w};
#pragma unroll
            for (int i = 0; i < 8; i++)
#pragma unroll
                for (int j = 0; j < 8; j++)
                    acc[i][j] = fmaf(a_[i], b_[j], acc[i][j]);
        }
        if (t+1 < nt){
            int nb = buf ^ 1;
            As[nb][acol+0][arow]=av.x; As[nb][acol+1][arow]=av.y;
            As[nb][acol+2][arow]=av.z; As[nb][acol+3][arow]=av.w;
            *reinterpret_cast<float4*>(&Bs[nb][bkr][bnc]) = bv;
            __syncthreads();
        }
    }

    // epilogue: float4 column groups (160 % 4 == 0 -> group never spans matrices)
#pragma unroll
    for (int jg = 0; jg < 2; jg++){
        int col = bn + tn + jg*4;
        if (col >= Ntot) continue;
        int m  = col / matcols;
        int c2 = col - m*matcols;
        const float* bp = (m==0)?bias0:(m==1)?bias1:(m==2)?bias2:bias3;
        float*       Cm = (m==0)?C0:(m==1)?C1:(m==2)?C2:C3;
        float4 bb = *reinterpret_cast<const float4*>(bp + c2);
#pragma unroll
        for (int i = 0; i < 8; i++){
            int row = bm + tm + i;
            if (row < M){
                float4 v;
                v.x = acc[i][jg*4+0] + bb.x;
                v.y = acc[i][jg*4+1] + bb.y;
                v.z = acc[i][jg*4+2] + bb.z;
                v.w = acc[i][jg*4+3] + bb.w;
                *reinterpret_cast<float4*>(Cm + (size_t)row*matcols + c2) = v;
            }
        }
    }
}

// ---------------- old fp32 GEMM (kept for the N=160 gate matmul) ----------------
__global__ __launch_bounds__(256) void k_gemm(
    const float* __restrict__ A, int lda, int M, int K,
    const float* __restrict__ B0, const float* __restrict__ B1,
    const float* __restrict__ B2, const float* __restrict__ B3,
    const float* __restrict__ bias0, const float* __restrict__ bias1,
    const float* __restrict__ bias2, const float* __restrict__ bias3,
    int matcols, int Ntot,
    float* __restrict__ C0, float* __restrict__ C1,
    float* __restrict__ C2, float* __restrict__ C3, int relu)
{
    __shared__ float As[16][132];
    __shared__ float Bs[16][64];
    int tid = threadIdx.x;
    int bm = blockIdx.y * 128, bn = blockIdx.x * 64;
    int tm8 = (tid >> 4) << 3;
    int tn4 = (tid & 15) << 2;
    float acc[8][4];
#pragma unroll
    for (int i = 0; i < 8; i++)
#pragma unroll
        for (int j = 0; j < 4; j++) acc[i][j] = 0.f;

    int ar  = tid >> 2;
    int ac4 = (tid & 3) << 2;
    int bkr = tid >> 4;
    int bcc = (tid & 15) << 2;
    int bcol = bn + bcc;
    const float* Bm = nullptr;
    int bc2 = 0;
    if (bcol < Ntot){
        int m = bcol / matcols;
        bc2 = bcol - m * matcols;
        Bm = (m == 0) ? B0 : (m == 1) ? B1 : (m == 2) ? B2 : B3;
    }

    for (int k0 = 0; k0 < K; k0 += 16){
#pragma unroll
        for (int half = 0; half < 2; half++){
            int row = bm + ar + half*64;
            float4 av = make_float4(0.f,0.f,0.f,0.f);
            if (row < M) av = *reinterpret_cast<const float4*>(A + (size_t)row*lda + k0 + ac4);
            As[ac4+0][ar + half*64] = av.x;
            As[ac4+1][ar + half*64] = av.y;
            As[ac4+2][ar + half*64] = av.z;
            As[ac4+3][ar + half*64] = av.w;
        }
        {
            float4 bv = make_float4(0.f,0.f,0.f,0.f);
            if (Bm) bv = *reinterpret_cast<const float4*>(Bm + (size_t)(k0 + bkr)*matcols + bc2);
            *reinterpret_cast<float4*>(&Bs[bkr][bcc]) = bv;
        }
        __syncthreads();
#pragma unroll
        for (int kk = 0; kk < 16; kk++){
            float4 b4 = *reinterpret_cast<const float4*>(&Bs[kk][tn4]);
            float4 a0 = *reinterpret_cast<const float4*>(&As[kk][tm8]);
            float4 a1 = *reinterpret_cast<const float4*>(&As[kk][tm8+4]);
            float a_[8] = {a0.x,a0.y,a0.z,a0.w,a1.x,a1.y,a1.z,a1.w};
            float b_[4] = {b4.x,b4.y,b4.z,b4.w};
#pragma unroll
            for (int i = 0; i < 8; i++)
#pragma unroll
                for (int j = 0; j < 4; j++)
                    acc[i][j] = fmaf(a_[i], b_[j], acc[i][j]);
        }
        __syncthreads();
    }

#pragma unroll
    for (int j = 0; j < 4; j++){
        int col = bn + tn4 + j;
        if (col >= Ntot) continue;
        int m  = col / matcols;
        int c2 = col - m * matcols;
        const float* bp = (m == 0) ? bias0 : (m == 1) ? bias1 : (m == 2) ? bias2 : bias3;
        float* Cm      = (m == 0) ? C0 : (m == 1) ? C1 : (m == 2) ? C2 : C3;
        float bb = bp[c2];
#pragma unroll
        for (int i = 0; i < 8; i++){
            int row = bm + tm8 + i;
            if (row < M){
                float v = acc[i][j] + bb;
                if (relu) v = fmaxf(v, 0.f);
                Cm[(size_t)row*matcols + c2] = v;
            }
        }
    }
}

// ---------------- edge: alpha logits ----------------
__global__ __launch_bounds__(256) void k_edge_alpha(
    const float* __restrict__ ea,
    const float* __restrict__ We, const float* __restrict__ be)
{
    __shared__ float sWe[4*HID];
    __shared__ float sbe[HID];
    int t = threadIdx.x;
    for (int i = t; i < 4*HID; i += 256) sWe[i] = We[i];
    if (t < HID) sbe[t] = be[t];
    __syncthreads();
    int warp = t >> 5, lane = t & 31;
    int e = blockIdx.x*8 + warp;
    int src = g_ei32[e];
    int dst = g_ei32[Ee + e];
    float e0 = ea[e*4+0], e1 = ea[e*4+1], e2 = ea[e*4+2], e3 = ea[e*4+3];
    const float* qr = g_q + (size_t)dst*HID;
    const float* kr = g_k + (size_t)src*HID;
    int h = lane >> 3, o = lane & 7;
    int cb = h*Dd + o;
    float part = 0.f;
#pragma unroll
    for (int i = 0; i < 5; i++){
        int c = cb + 8*i;
        float ev = sbe[c] + e0*sWe[c] + e1*sWe[HID+c] + e2*sWe[2*HID+c] + e3*sWe[3*HID+c];
        part = fmaf(qr[c], kr[c] + ev, part);
    }
    part += __shfl_down_sync(0xffffffffu, part, 4, 8);
    part += __shfl_down_sync(0xffffffffu, part, 2, 8);
    part += __shfl_down_sync(0xffffffffu, part, 1, 8);
    if (o == 0)
        g_alpha[(size_t)e*4 + h] = part * 0.15811388300841897f;  // 1/sqrt(40)
}

// ---------------- per-node softmax over incoming edges (warp per node) ------
__global__ __launch_bounds__(256) void k_node_soft(){
    int t = threadIdx.x, warp = t >> 5, lane = t & 31;
    int n = blockIdx.x*8 + warp;
    int beg = g_rowptr[n], end = g_rowptr[n+1];
    int deg = end - beg;
    if (deg == 0) return;
    float4* al4 = reinterpret_cast<float4*>(g_alpha);

    float m0=-3.4e38f, m1=-3.4e38f, m2=-3.4e38f, m3=-3.4e38f;
    for (int i = lane; i < deg; i += 32){
        float4 a = al4[g_eid[beg + i]];
        m0 = fmaxf(m0, a.x); m1 = fmaxf(m1, a.y);
        m2 = fmaxf(m2, a.z); m3 = fmaxf(m3, a.w);
    }
#pragma unroll
    for (int off = 16; off; off >>= 1){
        m0 = fmaxf(m0, __shfl_xor_sync(0xffffffffu, m0, off));
        m1 = fmaxf(m1, __shfl_xor_sync(0xffffffffu, m1, off));
        m2 = fmaxf(m2, __shfl_xor_sync(0xffffffffu, m2, off));
        m3 = fmaxf(m3, __shfl_xor_sync(0xffffffffu, m3, off));
    }
    float s0=0.f, s1=0.f, s2=0.f, s3=0.f;
    for (int i = lane; i < deg; i += 32){
        int e = g_eid[beg + i];
        float4 a = al4[e];
        a.x = expf(a.x - m0); a.y = expf(a.y - m1);
        a.z = expf(a.z - m2); a.w = expf(a.w - m3);
        s0 += a.x; s1 += a.y; s2 += a.z; s3 += a.w;
        al4[e] = a;
    }
#pragma unroll
    for (int off = 16; off; off >>= 1){
        s0 += __shfl_xor_sync(0xffffffffu, s0, off);
        s1 += __shfl_xor_sync(0xffffffffu, s1, off);
        s2 += __shfl_xor_sync(0xffffffffu, s2, off);
        s3 += __shfl_xor_sync(0xffffffffu, s3, off);
    }
    float r0 = 1.f/s0, r1 = 1.f/s1, r2 = 1.f/s2, r3 = 1.f/s3;
    for (int i = lane; i < deg; i += 32){
        int e = g_eid[beg + i];
        float4 a = al4[e];
        a.x *= r0; a.y *= r1; a.z *= r2; a.w *= r3;
        al4[e] = a;
    }
}

// ---------------- per-node aggregation (block of 160 threads per node) ------
#define ECH 64
__global__ __launch_bounds__(HID) void k_node_aggr(
    const float* __restrict__ ea,
    const float* __restrict__ We, const float* __restrict__ be)
{
    __shared__ float sWe[4*HID];
    __shared__ float sbe[HID];
    __shared__ float4 s_ea[ECH];
    __shared__ float4 s_a[ECH];
    __shared__ int    s_src[ECH];
    int c = threadIdx.x;
    int n = blockIdx.x;
    for (int i = c; i < 4*HID; i += HID) sWe[i] = We[i];
    sbe[c] = be[c];
    int beg = g_rowptr[n], end = g_rowptr[n+1];
    int h = c / Dd;
    float acc = 0.f;
    const float4* ea4 = reinterpret_cast<const float4*>(ea);
    const float4* al4 = reinterpret_cast<const float4*>(g_alpha);

    for (int base = beg; base < end; base += ECH){
        int m = min(ECH, end - base);
        __syncthreads();
        if (c < m){
            int e = g_eid[base + c];
            s_src[c] = g_ei32[e];
            s_ea[c]  = ea4[e];
            s_a[c]   = al4[e];
        }
        __syncthreads();
        for (int j = 0; j < m; j++){
            float4 ej = s_ea[j];
            float w = reinterpret_cast<const float*>(&s_a[j])[h];
            float ev = sbe[c] + ej.x*sWe[c] + ej.y*sWe[HID+c]
                     + ej.z*sWe[2*HID+c] + ej.w*sWe[3*HID+c];
            acc = fmaf(g_v[(size_t)s_src[j]*HID + c] + ev, w, acc);
        }
    }
    g_out[(size_t)n*HID + c] = acc;
}

// ---------------- beta gate + combine ----------------
__global__ __launch_bounds__(256) void k_beta(const float* __restrict__ Wb, int l){
    int t = threadIdx.x, warp = t >> 5, lane = t & 31;
    int n = blockIdx.x*8 + warp;
    const float* o = g_out  + (size_t)n*HID;
    const float* r = g_skip + (size_t)n*HID;
    float oc[5], rc[5];
    float p = 0.f;
#pragma unroll
    for (int i = 0; i < 5; i++){
        int c = lane + 32*i;
        oc[i] = o[c]; rc[i] = r[c];
        p += oc[i]*Wb[c] + rc[i]*Wb[HID+c] + (oc[i]-rc[i])*Wb[2*HID+c];
    }
#pragma unroll
    for (int off = 16; off; off >>= 1) p += __shfl_xor_sync(0xffffffffu, p, off);
    float beta = 1.f/(1.f + expf(-p));
    float* hx = g_xc + (size_t)n*JK + (size_t)l*HID;
#pragma unroll
    for (int i = 0; i < 5; i++){
        int c = lane + 32*i;
        hx[c] = beta*rc[i] + (1.f - beta)*oc[i];
    }
}

// ---------------- pooling ----------------
__global__ void k_init_pool(){
    int idx = blockIdx.x*blockDim.x + threadIdx.x;
    if (idx < Gg){ g_gmax[idx] = 0u; g_gden[idx] = 0.f; }
    if (idx < Gg*JK) g_pooled[idx] = 0.f;
}

__global__ __launch_bounds__(256) void k_gate(const float* __restrict__ Wg2,
                                              const float* __restrict__ bg2){
    int t = threadIdx.x, warp = t >> 5, lane = t & 31;
    int n = blockIdx.x*8 + warp;
    const float* tp = g_out + (size_t)n*HID;
    float p = 0.f;
#pragma unroll
    for (int i = 0; i < 5; i++){
        int c = lane + 32*i;
        p = fmaf(tp[c], Wg2[c], p);
    }
#pragma unroll
    for (int off = 16; off; off >>= 1) p += __shfl_xor_sync(0xffffffffu, p, off);
    if (lane == 0){
        float gate = p + bg2[0];
        g_gate[n] = gate;
        atomicMax(&g_gmax[g_batch32[n]], fenc(gate));
    }
}

__global__ void k_ge(){
    __shared__ float s[Gg];
    int t = threadIdx.x;
    if (t < Gg) s[t] = 0.f;
    __syncthreads();
    int n = blockIdx.x*blockDim.x + t;
    if (n < Nn){
        int b = g_batch32[n];
        float ge = expf(g_gate[n] - fdec(g_gmax[b]));
        g_gate[n] = ge;
        atomicAdd(&s[b], ge);
    }
    __syncthreads();
    if (t < Gg) atomicAdd(&g_gden[t], s[t]);
}

__global__ void k_att(){
    int n = blockIdx.x*blockDim.x + threadIdx.x;
    if (n < Nn) g_gate[n] /= g_gden[g_batch32[n]];
}

__global__ __launch_bounds__(JK) void k_pool(){
    int c = threadIdx.x;
    int n0 = blockIdx.x*128;
    if (n0 >= Nn) return;
    int nend = min(n0 + 128, Nn);
    int curg = g_batch32[n0];
    float acc = 0.f;
    for (int n = n0; n < nend; n++){
        int g = g_batch32[n];
        if (g != curg){
            atomicAdd(&g_pooled[curg*JK + c], acc);
            acc = 0.f; curg = g;
        }
        acc = fmaf(g_gate[n], g_xc[(size_t)n*JK + c], acc);
    }
    atomicAdd(&g_pooled[curg*JK + c], acc);
}

__global__ __launch_bounds__(JK) void k_final(const float* __restrict__ Wh1,
                                              const float* __restrict__ bh1,
                                              const float* __restrict__ Wh2,
                                              const float* __restrict__ bh2,
                                              float* __restrict__ outp){
    __shared__ float p[JK];
    __shared__ float t1[JK];
    int g = blockIdx.x, c = threadIdx.x;
    p[c] = g_pooled[g*JK + c];
    __syncthreads();
    float acc = bh1[c];
    for (int k = 0; k < JK; k++) acc = fmaf(p[k], Wh1[k*JK + c], acc);
    t1[c] = fmaxf(acc, 0.f);
    __syncthreads();
    int warp = c >> 5, lane = c & 31;
    if (warp < 6){
        float s = 0.f;
        for (int k = lane; k < JK; k += 32) s = fmaf(t1[k], Wh2[k*6 + warp], s);
#pragma unroll
        for (int off = 16; off; off >>= 1) s += __shfl_xor_sync(0xffffffffu, s, off);
        if (lane == 0) outp[g*6 + warp] = s + bh2[warp];
    }
}

// ---------------- host ----------------
extern "C" void kernel_launch(void* const* d_in, const int* in_sizes, int n_in,
                              void* d_out, int out_size){
    const float* x     = (const float*)d_in[0];
    const void*  ei    = d_in[1];
    const float* ea    = (const float*)d_in[2];
    const void*  batch = d_in[3];
    const float* W_in  = (const float*)d_in[4];
    const float* b_in  = (const float*)d_in[5];
    const float* Wq    = (const float*)d_in[6];
    const float* bq    = (const float*)d_in[7];
    const float* Wk    = (const float*)d_in[8];
    const float* bk    = (const float*)d_in[9];
    const float* Wv    = (const float*)d_in[10];
    const float* bv    = (const float*)d_in[11];
    const float* We    = (const float*)d_in[12];
    const float* be    = (const float*)d_in[13];
    const float* Wskip = (const float*)d_in[14];
    const float* bskip = (const float*)d_in[15];
    const float* Wbeta = (const float*)d_in[16];
    const float* Wg1   = (const float*)d_in[17];
    const float* bg1   = (const float*)d_in[18];
    const float* Wg2   = (const float*)d_in[19];
    const float* bg2   = (const float*)d_in[20];
    const float* Wh1   = (const float*)d_in[21];
    const float* bh1   = (const float*)d_in[22];
    const float* Wh2   = (const float*)d_in[23];
    const float* bh2   = (const float*)d_in[24];
    float* outp = (float*)d_out;

    void *ph0, *pxc, *pout, *pq, *pk, *pv, *ps;
    cudaGetSymbolAddress(&ph0, g_h0);
    cudaGetSymbolAddress(&pxc, g_xc);
    cudaGetSymbolAddress(&pout, g_out);
    cudaGetSymbolAddress(&pq, g_q);
    cudaGetSymbolAddress(&pk, g_k);
    cudaGetSymbolAddress(&pv, g_v);
    cudaGetSymbolAddress(&ps, g_skip);
    float* h0  = (float*)ph0;
    float* xc  = (float*)pxc;
    float* tmp = (float*)pout;
    float* qp  = (float*)pq;
    float* kp  = (float*)pk;
    float* vp  = (float*)pv;
    float* sp  = (float*)ps;

    k_detect<<<1, 256>>>(ei);
    k_convert<<<(2*Ee + 255)/256, 256>>>(ei, batch);
    k_count<<<(Ee + 255)/256, 256>>>();
    k_scan1<<<NBLK, 256>>>();
    k_scan2<<<1, 256>>>();
    k_scan3<<<NBLK, 256>>>();
    k_fill<<<(Ee + 255)/256, 256>>>();

    k_input<<<Nn, HID>>>(x, W_in, b_in);

    for (int l = 0; l < 2; l++){
        const float* A = l ? xc : h0;
        int lda = l ? JK : HID;
        dim3 grid(640/128, (Nn + 127)/128);
        k_gemm2<<<grid, 256>>>(A, lda, Nn, HID,
            Wq + l*HID*HID, Wk + l*HID*HID, Wv + l*HID*HID, Wskip + l*HID*HID,
            bq + l*HID, bk + l*HID, bv + l*HID, bskip + l*HID,
            HID, 4*HID, qp, kp, vp, sp);
        k_edge_alpha<<<Ee/8, 256>>>(ea, We + l*4*HID, be + l*HID);
        k_node_soft<<<Nn/8, 256>>>();
        k_node_aggr<<<Nn, HID>>>(ea, We + l*4*HID, be + l*HID);
        k_beta<<<Nn/8, 256>>>(Wbeta + l*3*HID, l);
    }

    {
        dim3 grid((HID + 63)/64, (Nn + 127)/128);
        k_gemm<<<grid, 256>>>(xc, JK, Nn, JK,
            Wg1, Wg1, Wg1, Wg1, bg1, bg1, bg1, bg1,
            HID, HID, tmp, tmp, tmp, tmp, 1);
    }
    k_init_pool<<<40, 256>>>();
    k_gate<<<Nn/8, 256>>>(Wg2, bg2);
    k_ge<<<(Nn + 255)/256, 256>>>();
    k_att<<<(Nn + 255)/256, 256>>>();
    k_pool<<<(Nn + 127)/128, JK>>>();
    k_final<<<Gg, JK>>>(Wh1, bh1, Wh2, bh2, outp);
}

// round 6
// speedup vs baseline: 1.3894x; 1.1993x over previous
#include <cuda_runtime.h>
#include <math.h>

#define Nn 50000
#define Ee 500000
#define Gg 32
#define Hh 4
#define Dd 40
#define HID 160
#define JK 320
#define NBLK 196   // ceil(Nn/256)

// ---------------- scratch ----------------
__device__ float    g_h0[(size_t)Nn*HID];
__device__ float    g_q[(size_t)Nn*HID];
__device__ float    g_k[(size_t)Nn*HID];
__device__ float    g_v[(size_t)Nn*HID];
__device__ float    g_skip[(size_t)Nn*HID];
__device__ float    g_out[(size_t)Nn*HID];
__device__ float    g_xc[(size_t)Nn*JK];
__device__ float    g_alpha[(size_t)Ee*Hh];
__device__ float    g_gate[Nn];
__device__ unsigned g_gmax[Gg];
__device__ float    g_gden[Gg];
__device__ float    g_pooled[Gg*JK];
__device__ int      g_ei32[(size_t)2*Ee];
__device__ int      g_batch32[Nn];
__device__ int      g_is64;
__device__ int      g_cnt[Nn];
__device__ int      g_rowptr[Nn+1];
__device__ int      g_fill[Nn];
__device__ int      g_eid[Ee];
__device__ int      g_bsum[NBLK];
__device__ int      g_boff[NBLK];

__device__ __forceinline__ unsigned fenc(float f){
    unsigned u = __float_as_uint(f);
    return (u & 0x80000000u) ? ~u : (u | 0x80000000u);
}
__device__ __forceinline__ float fdec(unsigned e){
    return (e & 0x80000000u) ? __uint_as_float(e ^ 0x80000000u) : __uint_as_float(~e);
}
__device__ __forceinline__ unsigned f2tf32(float f){
    unsigned u;
    asm("cvt.rna.tf32.f32 %0, %1;" : "=r"(u) : "f"(f));
    return u;
}

// ---------------- dtype detection + index normalization ----------------
__global__ void k_detect(const void* __restrict__ ei){
    const long long* p = (const long long*)ei;
    int bad = 0;
    for (int i = threadIdx.x; i < 4096; i += 256){
        long long v = p[i];
        if (v < 0 || v >= Nn) bad = 1;
    }
    bad = __syncthreads_or(bad);
    if (threadIdx.x == 0) g_is64 = bad ? 0 : 1;
}

__global__ void k_convert(const void* __restrict__ ei, const void* __restrict__ batch){
    int idx = blockIdx.x*blockDim.x + threadIdx.x;
    int is64 = g_is64;
    if (idx < 2*Ee){
        g_ei32[idx] = is64 ? (int)((const long long*)ei)[idx]
                           : ((const int*)ei)[idx];
    }
    if (idx < Nn){
        g_batch32[idx] = is64 ? (int)((const long long*)batch)[idx]
                              : ((const int*)batch)[idx];
        g_cnt[idx] = 0;
    }
}

// ---------------- CSR build ----------------
__global__ void k_count(){
    int e = blockIdx.x*blockDim.x + threadIdx.x;
    if (e < Ee) atomicAdd(&g_cnt[g_ei32[Ee + e]], 1);
}

__global__ __launch_bounds__(256) void k_scan1(){
    __shared__ int s[256];
    int t = threadIdx.x;
    int idx = blockIdx.x*256 + t;
    int v = (idx < Nn) ? g_cnt[idx] : 0;
    s[t] = v; __syncthreads();
#pragma unroll
    for (int off = 1; off < 256; off <<= 1){
        int x = (t >= off) ? s[t-off] : 0;
        __syncthreads();
        s[t] += x;
        __syncthreads();
    }
    if (idx < Nn) g_rowptr[idx] = s[t] - v;
    if (t == 255) g_bsum[blockIdx.x] = s[255];
}

__global__ __launch_bounds__(256) void k_scan2(){
    __shared__ int s[256];
    int t = threadIdx.x;
    int v = (t < NBLK) ? g_bsum[t] : 0;
    s[t] = v; __syncthreads();
#pragma unroll
    for (int off = 1; off < 256; off <<= 1){
        int x = (t >= off) ? s[t-off] : 0;
        __syncthreads();
        s[t] += x;
        __syncthreads();
    }
    if (t < NBLK) g_boff[t] = s[t] - v;
}

__global__ void k_scan3(){
    int idx = blockIdx.x*blockDim.x + threadIdx.x;
    if (idx < Nn){
        int r = g_rowptr[idx] + g_boff[idx >> 8];
        g_rowptr[idx] = r;
        g_fill[idx] = r;
    }
    if (idx == 0) g_rowptr[Nn] = Ee;
}

__global__ void k_fill(){
    int e = blockIdx.x*blockDim.x + threadIdx.x;
    if (e < Ee){
        int slot = atomicAdd(&g_fill[g_ei32[Ee + e]], 1);
        g_eid[slot] = e;
    }
}

// ---------------- input projection ----------------
__global__ __launch_bounds__(HID) void k_input(const float* __restrict__ x,
                                               const float* __restrict__ W,
                                               const float* __restrict__ b){
    int n = blockIdx.x, c = threadIdx.x;
    __shared__ float xr[5];
    if (c < 5) xr[c] = x[n*5 + c];
    __syncthreads();
    float acc = b[c];
#pragma unroll
    for (int j = 0; j < 5; j++) acc = fmaf(xr[j], W[j*HID + c], acc);
    g_h0[(size_t)n*HID + c] = acc;
}

// ---------------- TF32 tensor-core GEMM ----------------
// C = A[M,K] @ [B0|B1|B2|B3] + bias (opt relu). K % 32 == 0.
// Block tile 128(M)x128(N), 8 warps in 2(M)x4(N), each warp 64x32 via
// 4x4 grid of mma.m16n8k8. A/B staged in smem as tf32 bits.
#define SA_STR 36
#define SB_STR 136
__global__ __launch_bounds__(256,2) void k_gemm_tf32(
    const float* __restrict__ A, int lda, int M, int K,
    const float* __restrict__ B0, const float* __restrict__ B1,
    const float* __restrict__ B2, const float* __restrict__ B3,
    const float* __restrict__ bias0, const float* __restrict__ bias1,
    const float* __restrict__ bias2, const float* __restrict__ bias3,
    int matcols, int Ntot,
    float* __restrict__ C0, float* __restrict__ C1,
    float* __restrict__ C2, float* __restrict__ C3, int relu)
{
    __shared__ unsigned sA[128*SA_STR];
    __shared__ unsigned sB[32*SB_STR];
    int tid = threadIdx.x;
    int bm = blockIdx.y*128, bn = blockIdx.x*128;
    int warp = tid >> 5, lane = tid & 31;
    int wm = (warp & 1)*64, wn = (warp >> 1)*32;
    int g = lane >> 2, l4 = lane & 3;

    float acc[4][4][4];
#pragma unroll
    for (int i = 0; i < 4; i++)
#pragma unroll
        for (int j = 0; j < 4; j++)
#pragma unroll
            for (int r = 0; r < 4; r++) acc[i][j][r] = 0.f;

    // B column selection for the 4 loader slots this thread covers
    for (int k0 = 0; k0 < K; k0 += 32){
        // stage A: 128 rows x 32 cols = 1024 float4
#pragma unroll
        for (int r = 0; r < 4; r++){
            int s = tid + 256*r;
            int row = s >> 3, c4 = (s & 7) << 2;
            float4 v = make_float4(0.f,0.f,0.f,0.f);
            if (bm + row < M)
                v = *reinterpret_cast<const float4*>(A + (size_t)(bm+row)*lda + k0 + c4);
            uint4 u;
            u.x = f2tf32(v.x); u.y = f2tf32(v.y); u.z = f2tf32(v.z); u.w = f2tf32(v.w);
            *reinterpret_cast<uint4*>(&sA[row*SA_STR + c4]) = u;
        }
        // stage B: 32 k x 128 n = 1024 float4
#pragma unroll
        for (int r = 0; r < 4; r++){
            int s = tid + 256*r;
            int kr = s >> 5, nc = (s & 31) << 2;
            int col = bn + nc;
            float4 v = make_float4(0.f,0.f,0.f,0.f);
            if (col < Ntot){
                int m  = col / matcols;
                int c2 = col - m*matcols;
                const float* Bm = (m==0)?B0:(m==1)?B1:(m==2)?B2:B3;
                v = *reinterpret_cast<const float4*>(Bm + (size_t)(k0+kr)*matcols + c2);
            }
            uint4 u;
            u.x = f2tf32(v.x); u.y = f2tf32(v.y); u.z = f2tf32(v.z); u.w = f2tf32(v.w);
            *reinterpret_cast<uint4*>(&sB[kr*SB_STR + nc]) = u;
        }
        __syncthreads();

#pragma unroll
        for (int k8 = 0; k8 < 4; k8++){
            unsigned a[4][4], b[4][2];
            int c0 = k8*8 + l4;
#pragma unroll
            for (int i = 0; i < 4; i++){
                int r0 = wm + i*16 + g;
                a[i][0] = sA[r0*SA_STR + c0];
                a[i][1] = sA[(r0+8)*SA_STR + c0];
                a[i][2] = sA[r0*SA_STR + c0 + 4];
                a[i][3] = sA[(r0+8)*SA_STR + c0 + 4];
            }
#pragma unroll
            for (int j = 0; j < 4; j++){
                int nn = wn + j*8 + g;
                b[j][0] = sB[(k8*8 + l4)*SB_STR + nn];
                b[j][1] = sB[(k8*8 + l4 + 4)*SB_STR + nn];
            }
#pragma unroll
            for (int i = 0; i < 4; i++)
#pragma unroll
                for (int j = 0; j < 4; j++){
                    asm volatile(
                        "mma.sync.aligned.m16n8k8.row.col.f32.tf32.tf32.f32 "
                        "{%0,%1,%2,%3}, {%4,%5,%6,%7}, {%8,%9}, {%0,%1,%2,%3};\n"
                        : "+f"(acc[i][j][0]), "+f"(acc[i][j][1]),
                          "+f"(acc[i][j][2]), "+f"(acc[i][j][3])
                        : "r"(a[i][0]), "r"(a[i][1]), "r"(a[i][2]), "r"(a[i][3]),
                          "r"(b[j][0]), "r"(b[j][1]));
                }
        }
        __syncthreads();
    }

    // epilogue: per mma tile, lane writes (row g, cols 2*l4) and (row g+8)
#pragma unroll
    for (int j = 0; j < 4; j++){
        int col = bn + wn + j*8 + 2*l4;
        if (col >= Ntot) continue;
        int m  = col / matcols;
        int c2 = col - m*matcols;
        const float* bp = (m==0)?bias0:(m==1)?bias1:(m==2)?bias2:bias3;
        float*       Cm = (m==0)?C0:(m==1)?C1:(m==2)?C2:C3;
        float bx = bp[c2], by = bp[c2+1];
#pragma unroll
        for (int i = 0; i < 4; i++){
            int row0 = bm + wm + i*16 + g;
            float vx, vy;
            if (row0 < M){
                vx = acc[i][j][0] + bx; vy = acc[i][j][1] + by;
                if (relu){ vx = fmaxf(vx, 0.f); vy = fmaxf(vy, 0.f); }
                float2 o = make_float2(vx, vy);
                *reinterpret_cast<float2*>(Cm + (size_t)row0*matcols + c2) = o;
            }
            int row1 = row0 + 8;
            if (row1 < M){
                vx = acc[i][j][2] + bx; vy = acc[i][j][3] + by;
                if (relu){ vx = fmaxf(vx, 0.f); vy = fmaxf(vy, 0.f); }
                float2 o = make_float2(vx, vy);
                *reinterpret_cast<float2*>(Cm + (size_t)row1*matcols + c2) = o;
            }
        }
    }
}

// ---------------- edge: alpha logits ----------------
__global__ __launch_bounds__(256) void k_edge_alpha(
    const float* __restrict__ ea,
    const float* __restrict__ We, const float* __restrict__ be)
{
    __shared__ float sWe[4*HID];
    __shared__ float sbe[HID];
    int t = threadIdx.x;
    for (int i = t; i < 4*HID; i += 256) sWe[i] = We[i];
    if (t < HID) sbe[t] = be[t];
    __syncthreads();
    int warp = t >> 5, lane = t & 31;
    int e = blockIdx.x*8 + warp;
    int src = g_ei32[e];
    int dst = g_ei32[Ee + e];
    float e0 = ea[e*4+0], e1 = ea[e*4+1], e2 = ea[e*4+2], e3 = ea[e*4+3];
    const float* qr = g_q + (size_t)dst*HID;
    const float* kr = g_k + (size_t)src*HID;
    int h = lane >> 3, o = lane & 7;
    int cb = h*Dd + o;
    float part = 0.f;
#pragma unroll
    for (int i = 0; i < 5; i++){
        int c = cb + 8*i;
        float ev = sbe[c] + e0*sWe[c] + e1*sWe[HID+c] + e2*sWe[2*HID+c] + e3*sWe[3*HID+c];
        part = fmaf(qr[c], kr[c] + ev, part);
    }
    part += __shfl_down_sync(0xffffffffu, part, 4, 8);
    part += __shfl_down_sync(0xffffffffu, part, 2, 8);
    part += __shfl_down_sync(0xffffffffu, part, 1, 8);
    if (o == 0)
        g_alpha[(size_t)e*4 + h] = part * 0.15811388300841897f;
}

// ---------------- per-node softmax ----------------
__global__ __launch_bounds__(256) void k_node_soft(){
    int t = threadIdx.x, warp = t >> 5, lane = t & 31;
    int n = blockIdx.x*8 + warp;
    int beg = g_rowptr[n], end = g_rowptr[n+1];
    int deg = end - beg;
    if (deg == 0) return;
    float4* al4 = reinterpret_cast<float4*>(g_alpha);

    float m0=-3.4e38f, m1=-3.4e38f, m2=-3.4e38f, m3=-3.4e38f;
    for (int i = lane; i < deg; i += 32){
        float4 a = al4[g_eid[beg + i]];
        m0 = fmaxf(m0, a.x); m1 = fmaxf(m1, a.y);
        m2 = fmaxf(m2, a.z); m3 = fmaxf(m3, a.w);
    }
#pragma unroll
    for (int off = 16; off; off >>= 1){
        m0 = fmaxf(m0, __shfl_xor_sync(0xffffffffu, m0, off));
        m1 = fmaxf(m1, __shfl_xor_sync(0xffffffffu, m1, off));
        m2 = fmaxf(m2, __shfl_xor_sync(0xffffffffu, m2, off));
        m3 = fmaxf(m3, __shfl_xor_sync(0xffffffffu, m3, off));
    }
    float s0=0.f, s1=0.f, s2=0.f, s3=0.f;
    for (int i = lane; i < deg; i += 32){
        int e = g_eid[beg + i];
        float4 a = al4[e];
        a.x = expf(a.x - m0); a.y = expf(a.y - m1);
        a.z = expf(a.z - m2); a.w = expf(a.w - m3);
        s0 += a.x; s1 += a.y; s2 += a.z; s3 += a.w;
        al4[e] = a;
    }
#pragma unroll
    for (int off = 16; off; off >>= 1){
        s0 += __shfl_xor_sync(0xffffffffu, s0, off);
        s1 += __shfl_xor_sync(0xffffffffu, s1, off);
        s2 += __shfl_xor_sync(0xffffffffu, s2, off);
        s3 += __shfl_xor_sync(0xffffffffu, s3, off);
    }
    float r0 = 1.f/s0, r1 = 1.f/s1, r2 = 1.f/s2, r3 = 1.f/s3;
    for (int i = lane; i < deg; i += 32){
        int e = g_eid[beg + i];
        float4 a = al4[e];
        a.x *= r0; a.y *= r1; a.z *= r2; a.w *= r3;
        al4[e] = a;
    }
}

// ---------------- per-node aggregation ----------------
#define ECH 64
__global__ __launch_bounds__(HID) void k_node_aggr(
    const float* __restrict__ ea,
    const float* __restrict__ We, const float* __restrict__ be)
{
    __shared__ float sWe[4*HID];
    __shared__ float sbe[HID];
    __shared__ float4 s_ea[ECH];
    __shared__ float4 s_a[ECH];
    __shared__ int    s_src[ECH];
    int c = threadIdx.x;
    int n = blockIdx.x;
    for (int i = c; i < 4*HID; i += HID) sWe[i] = We[i];
    sbe[c] = be[c];
    int beg = g_rowptr[n], end = g_rowptr[n+1];
    int h = c / Dd;
    float acc = 0.f;
    const float4* ea4 = reinterpret_cast<const float4*>(ea);
    const float4* al4 = reinterpret_cast<const float4*>(g_alpha);

    for (int base = beg; base < end; base += ECH){
        int m = min(ECH, end - base);
        __syncthreads();
        if (c < m){
            int e = g_eid[base + c];
            s_src[c] = g_ei32[e];
            s_ea[c]  = ea4[e];
            s_a[c]   = al4[e];
        }
        __syncthreads();
        for (int j = 0; j < m; j++){
            float4 ej = s_ea[j];
            float w = reinterpret_cast<const float*>(&s_a[j])[h];
            float ev = sbe[c] + ej.x*sWe[c] + ej.y*sWe[HID+c]
                     + ej.z*sWe[2*HID+c] + ej.w*sWe[3*HID+c];
            acc = fmaf(g_v[(size_t)s_src[j]*HID + c] + ev, w, acc);
        }
    }
    g_out[(size_t)n*HID + c] = acc;
}

// ---------------- beta gate + combine ----------------
__global__ __launch_bounds__(256) void k_beta(const float* __restrict__ Wb, int l){
    int t = threadIdx.x, warp = t >> 5, lane = t & 31;
    int n = blockIdx.x*8 + warp;
    const float* o = g_out  + (size_t)n*HID;
    const float* r = g_skip + (size_t)n*HID;
    float oc[5], rc[5];
    float p = 0.f;
#pragma unroll
    for (int i = 0; i < 5; i++){
        int c = lane + 32*i;
        oc[i] = o[c]; rc[i] = r[c];
        p += oc[i]*Wb[c] + rc[i]*Wb[HID+c] + (oc[i]-rc[i])*Wb[2*HID+c];
    }
#pragma unroll
    for (int off = 16; off; off >>= 1) p += __shfl_xor_sync(0xffffffffu, p, off);
    float beta = 1.f/(1.f + expf(-p));
    float* hx = g_xc + (size_t)n*JK + (size_t)l*HID;
#pragma unroll
    for (int i = 0; i < 5; i++){
        int c = lane + 32*i;
        hx[c] = beta*rc[i] + (1.f - beta)*oc[i];
    }
}

// ---------------- pooling ----------------
__global__ void k_init_pool(){
    int idx = blockIdx.x*blockDim.x + threadIdx.x;
    if (idx < Gg){ g_gmax[idx] = 0u; g_gden[idx] = 0.f; }
    if (idx < Gg*JK) g_pooled[idx] = 0.f;
}

__global__ __launch_bounds__(256) void k_gate(const float* __restrict__ Wg2,
                                              const float* __restrict__ bg2){
    int t = threadIdx.x, warp = t >> 5, lane = t & 31;
    int n = blockIdx.x*8 + warp;
    const float* tp = g_out + (size_t)n*HID;
    float p = 0.f;
#pragma unroll
    for (int i = 0; i < 5; i++){
        int c = lane + 32*i;
        p = fmaf(tp[c], Wg2[c], p);
    }
#pragma unroll
    for (int off = 16; off; off >>= 1) p += __shfl_xor_sync(0xffffffffu, p, off);
    if (lane == 0){
        float gate = p + bg2[0];
        g_gate[n] = gate;
        atomicMax(&g_gmax[g_batch32[n]], fenc(gate));
    }
}

__global__ void k_ge(){
    __shared__ float s[Gg];
    int t = threadIdx.x;
    if (t < Gg) s[t] = 0.f;
    __syncthreads();
    int n = blockIdx.x*blockDim.x + t;
    if (n < Nn){
        int b = g_batch32[n];
        float ge = expf(g_gate[n] - fdec(g_gmax[b]));
        g_gate[n] = ge;
        atomicAdd(&s[b], ge);
    }
    __syncthreads();
    if (t < Gg) atomicAdd(&g_gden[t], s[t]);
}

__global__ void k_att(){
    int n = blockIdx.x*blockDim.x + threadIdx.x;
    if (n < Nn) g_gate[n] /= g_gden[g_batch32[n]];
}

__global__ __launch_bounds__(JK) void k_pool(){
    int c = threadIdx.x;
    int n0 = blockIdx.x*128;
    if (n0 >= Nn) return;
    int nend = min(n0 + 128, Nn);
    int curg = g_batch32[n0];
    float acc = 0.f;
    for (int n = n0; n < nend; n++){
        int g = g_batch32[n];
        if (g != curg){
            atomicAdd(&g_pooled[curg*JK + c], acc);
            acc = 0.f; curg = g;
        }
        acc = fmaf(g_gate[n], g_xc[(size_t)n*JK + c], acc);
    }
    atomicAdd(&g_pooled[curg*JK + c], acc);
}

__global__ __launch_bounds__(JK) void k_final(const float* __restrict__ Wh1,
                                              const float* __restrict__ bh1,
                                              const float* __restrict__ Wh2,
                                              const float* __restrict__ bh2,
                                              float* __restrict__ outp){
    __shared__ float p[JK];
    __shared__ float t1[JK];
    int g = blockIdx.x, c = threadIdx.x;
    p[c] = g_pooled[g*JK + c];
    __syncthreads();
    float acc = bh1[c];
    for (int k = 0; k < JK; k++) acc = fmaf(p[k], Wh1[k*JK + c], acc);
    t1[c] = fmaxf(acc, 0.f);
    __syncthreads();
    int warp = c >> 5, lane = c & 31;
    if (warp < 6){
        float s = 0.f;
        for (int k = lane; k < JK; k += 32) s = fmaf(t1[k], Wh2[k*6 + warp], s);
#pragma unroll
        for (int off = 16; off; off >>= 1) s += __shfl_xor_sync(0xffffffffu, s, off);
        if (lane == 0) outp[g*6 + warp] = s + bh2[warp];
    }
}

// ---------------- host ----------------
extern "C" void kernel_launch(void* const* d_in, const int* in_sizes, int n_in,
                              void* d_out, int out_size){
    const float* x     = (const float*)d_in[0];
    const void*  ei    = d_in[1];
    const float* ea    = (const float*)d_in[2];
    const void*  batch = d_in[3];
    const float* W_in  = (const float*)d_in[4];
    const float* b_in  = (const float*)d_in[5];
    const float* Wq    = (const float*)d_in[6];
    const float* bq    = (const float*)d_in[7];
    const float* Wk    = (const float*)d_in[8];
    const float* bk    = (const float*)d_in[9];
    const float* Wv    = (const float*)d_in[10];
    const float* bv    = (const float*)d_in[11];
    const float* We    = (const float*)d_in[12];
    const float* be    = (const float*)d_in[13];
    const float* Wskip = (const float*)d_in[14];
    const float* bskip = (const float*)d_in[15];
    const float* Wbeta = (const float*)d_in[16];
    const float* Wg1   = (const float*)d_in[17];
    const float* bg1   = (const float*)d_in[18];
    const float* Wg2   = (const float*)d_in[19];
    const float* bg2   = (const float*)d_in[20];
    const float* Wh1   = (const float*)d_in[21];
    const float* bh1   = (const float*)d_in[22];
    const float* Wh2   = (const float*)d_in[23];
    const float* bh2   = (const float*)d_in[24];
    float* outp = (float*)d_out;

    void *ph0, *pxc, *pout, *pq, *pk, *pv, *ps;
    cudaGetSymbolAddress(&ph0, g_h0);
    cudaGetSymbolAddress(&pxc, g_xc);
    cudaGetSymbolAddress(&pout, g_out);
    cudaGetSymbolAddress(&pq, g_q);
    cudaGetSymbolAddress(&pk, g_k);
    cudaGetSymbolAddress(&pv, g_v);
    cudaGetSymbolAddress(&ps, g_skip);
    float* h0  = (float*)ph0;
    float* xc  = (float*)pxc;
    float* tmp = (float*)pout;
    float* qp  = (float*)pq;
    float* kp  = (float*)pk;
    float* vp  = (float*)pv;
    float* sp  = (float*)ps;

    k_detect<<<1, 256>>>(ei);
    k_convert<<<(2*Ee + 255)/256, 256>>>(ei, batch);
    k_count<<<(Ee + 255)/256, 256>>>();
    k_scan1<<<NBLK, 256>>>();
    k_scan2<<<1, 256>>>();
    k_scan3<<<NBLK, 256>>>();
    k_fill<<<(Ee + 255)/256, 256>>>();

    k_input<<<Nn, HID>>>(x, W_in, b_in);

    for (int l = 0; l < 2; l++){
        const float* A = l ? xc : h0;
        int lda = l ? JK : HID;
        dim3 grid(5, (Nn + 127)/128);
        k_gemm_tf32<<<grid, 256>>>(A, lda, Nn, HID,
            Wq + l*HID*HID, Wk + l*HID*HID, Wv + l*HID*HID, Wskip + l*HID*HID,
            bq + l*HID, bk + l*HID, bv + l*HID, bskip + l*HID,
            HID, 4*HID, qp, kp, vp, sp, 0);
        k_edge_alpha<<<Ee/8, 256>>>(ea, We + l*4*HID, be + l*HID);
        k_node_soft<<<Nn/8, 256>>>();
        k_node_aggr<<<Nn, HID>>>(ea, We + l*4*HID, be + l*HID);
        k_beta<<<Nn/8, 256>>>(Wbeta + l*3*HID, l);
    }

    {
        dim3 grid(2, (Nn + 127)/128);
        k_gemm_tf32<<<grid, 256>>>(xc, JK, Nn, JK,
            Wg1, Wg1, Wg1, Wg1, bg1, bg1, bg1, bg1,
            HID, HID, tmp, tmp, tmp, tmp, 1);
    }
    k_init_pool<<<40, 256>>>();
    k_gate<<<Nn/8, 256>>>(Wg2, bg2);
    k_ge<<<(Nn + 255)/256, 256>>>();
    k_att<<<(Nn + 255)/256, 256>>>();
    k_pool<<<(Nn + 127)/128, JK>>>();
    k_final<<<Gg, JK>>>(Wh1, bh1, Wh2, bh2, outp);
}